// round 3
// baseline (speedup 1.0000x reference)
#include <cuda_runtime.h>

// TwoRobots Euler step, affine form. R3: exact-fill grid-stride (1184 CTAs =
// 148 SMs x 8 blocks) to kill wave-transition overhead + streaming ld/st hints.
//
// pair p in {0..3} -> pos row {0,1,4,5}, vel row pos+2, ctrl row p.
//   o_pos = pos + H*vel + w_pos
//   o_vel = vel + H*(-KS*(pos - xbar[pos_row]) - CD*vel + u) + w_vel

#define HSTEP 0.05f
#define KS    2.0f
#define CD    2.0f

#define NSMS      148
#define BLK_PER_SM  8
#define THREADS   256

__global__ __launch_bounds__(THREADS, BLK_PER_SM)
void tworobots_pair_gs(const float4* __restrict__ x,
                       const float4* __restrict__ u,
                       const float4* __restrict__ w,
                       const float*  __restrict__ xbar,
                       float4* __restrict__ out,
                       int n4)
{
    const int pair = blockIdx.y;                 // 0..3
    const int pr   = pair + ((pair >> 1) << 1);  // 0,1,4,5
    const int vr   = pr + 2;                     // 2,3,6,7

    const float xb = __ldg(&xbar[pr]);

    const float4* __restrict__ xpP = x + (size_t)pr   * n4;
    const float4* __restrict__ xvP = x + (size_t)vr   * n4;
    const float4* __restrict__ uP  = u + (size_t)pair * n4;
    const float4* __restrict__ wpP = w + (size_t)pr   * n4;
    const float4* __restrict__ wvP = w + (size_t)vr   * n4;
    float4* __restrict__ opP = out + (size_t)pr * n4;
    float4* __restrict__ ovP = out + (size_t)vr * n4;

    const int stride = gridDim.x * blockDim.x;

    for (int i = blockIdx.x * blockDim.x + threadIdx.x; i < n4; i += stride) {
        // 5 independent streaming loads, front-batched by ptxas.
        const float4 xp = __ldcs(xpP + i);
        const float4 xv = __ldcs(xvP + i);
        const float4 uu = __ldcs(uP  + i);
        const float4 wp = __ldcs(wpP + i);
        const float4 wv = __ldcs(wvP + i);

        float4 op, ov;
#define LANE(c)                                                  \
        {                                                        \
            float fg = fmaf(-KS, (xp.c - xb), -CD * xv.c);       \
            op.c = fmaf(HSTEP, xv.c, xp.c) + wp.c;               \
            ov.c = fmaf(HSTEP, (fg + uu.c), xv.c) + wv.c;        \
        }
        LANE(x) LANE(y) LANE(z) LANE(w)
#undef LANE

        __stcs(opP + i, op);
        __stcs(ovP + i, ov);
    }
}

// Scalar fallback (B % 4 != 0) — same structure.
__global__ __launch_bounds__(THREADS, BLK_PER_SM)
void tworobots_pair_gs_scalar(const float* __restrict__ x,
                              const float* __restrict__ u,
                              const float* __restrict__ w,
                              const float* __restrict__ xbar,
                              float* __restrict__ out,
                              int B)
{
    const int pair = blockIdx.y;
    const int pr   = pair + ((pair >> 1) << 1);
    const int vr   = pr + 2;

    const float xb = __ldg(&xbar[pr]);
    const int stride = gridDim.x * blockDim.x;

    for (int i = blockIdx.x * blockDim.x + threadIdx.x; i < B; i += stride) {
        const float xp = __ldcs(x + (size_t)pr   * B + i);
        const float xv = __ldcs(x + (size_t)vr   * B + i);
        const float uu = __ldcs(u + (size_t)pair * B + i);
        const float wp = __ldcs(w + (size_t)pr   * B + i);
        const float wv = __ldcs(w + (size_t)vr   * B + i);

        float fg = fmaf(-KS, (xp - xb), -CD * xv);
        __stcs(out + (size_t)pr * B + i, fmaf(HSTEP, xv, xp) + wp);
        __stcs(out + (size_t)vr * B + i, fmaf(HSTEP, (fg + uu), xv) + wv);
    }
}

extern "C" void kernel_launch(void* const* d_in, const int* in_sizes, int n_in,
                              void* d_out, int out_size)
{
    const float* x    = (const float*)d_in[0];   // [8, B]
    const float* u    = (const float*)d_in[1];   // [4, B]
    const float* w    = (const float*)d_in[2];   // [8, B]
    const float* xbar = (const float*)d_in[3];   // [8]
    float* out = (float*)d_out;                  // [8, B]

    const int B = in_sizes[0] / 8;

    // Exact-fill: 148 SMs * 8 blocks = 1184 CTAs total, split 4 ways (pairs).
    const int gx = (NSMS * BLK_PER_SM) / 4;      // 296 per pair

    if ((B & 3) == 0) {
        const int n4 = B / 4;
        dim3 grid(gx, 4);
        tworobots_pair_gs<<<grid, THREADS>>>((const float4*)x, (const float4*)u,
                                             (const float4*)w, xbar,
                                             (float4*)out, n4);
    } else {
        dim3 grid(gx, 4);
        tworobots_pair_gs_scalar<<<grid, THREADS>>>(x, u, w, xbar, out, B);
    }
}